// round 1
// baseline (speedup 1.0000x reference)
#include <cuda_runtime.h>

#define KCAP 3
#define LSEQ 200
#define DDIM 64
#define LP   65   // padded M row stride (banks)

// smem layout (floats):
//   Ws[64*64]  Ms[200*65]  Es[40*64]  logits[600]  wts[600]  cand[192]  fac[4]
#define SMEM_FLOATS (64*64 + LSEQ*LP + 40*64 + 600 + 600 + 192 + 4)

__global__ __launch_bounds__(256, 2)
void caps_kernel(const float* __restrict__ E,
                 const float* __restrict__ Wg,
                 const float* __restrict__ Lg,
                 const int*   __restrict__ SL,
                 float* __restrict__ out)
{
    extern __shared__ float sm[];
    float* Ws     = sm;                    // 4096
    float* Ms     = Ws + 64*64;            // 13000
    float* Es     = Ms + LSEQ*LP;          // 2560
    float* logits = Es + 40*64;            // 600
    float* wts    = logits + 600;          // 600
    float* cand   = wts + 600;             // 192
    float* fac    = cand + 192;            // 4

    const int n = blockIdx.x;
    const int t = threadIdx.x;             // 0..255
    const int c = t & 63;                  // column 0..63
    const int g = t >> 6;                  // row group 0..3

    // ---- load W (16KB) + logits (2.4KB) ----
    {
        const float4* w4 = reinterpret_cast<const float4*>(Wg);
        float4* s4 = reinterpret_cast<float4*>(Ws);
        #pragma unroll
        for (int i = 0; i < 4; i++) s4[t + 256*i] = w4[t + 256*i];
        const float* lg = Lg + n*600;
        #pragma unroll
        for (int i = t; i < 600; i += 256) logits[i] = lg[i];
    }
    const int sl = SL[n];
    __syncthreads();

    // ---- Phase B: M[l][c] = sum_d E[l][d] * W[d][c], staged 40-row chunks ----
    const float* En = E + (size_t)n * LSEQ * DDIM;
    for (int base = 0; base < LSEQ; base += 40) {
        const float4* e4 = reinterpret_cast<const float4*>(En + base*DDIM);
        float4* es4 = reinterpret_cast<float4*>(Es);
        for (int i = t; i < 640; i += 256) es4[i] = e4[i];   // 40*64/4
        __syncthreads();

        float acc[10];
        #pragma unroll
        for (int r = 0; r < 10; r++) acc[r] = 0.f;
        #pragma unroll 8
        for (int d = 0; d < 64; d++) {
            const float w = Ws[d*64 + c];                    // conflict-free
            #pragma unroll
            for (int r = 0; r < 10; r++)                      // Es: warp-uniform bcast
                acc[r] = fmaf(Es[(g + 4*r)*64 + d], w, acc[r]);
        }
        #pragma unroll
        for (int r = 0; r < 10; r++)
            Ms[(base + g + 4*r)*LP + c] = acc[r];
        __syncthreads();
    }

    // ---- Phase C: 3 routing iterations entirely in smem ----
    #pragma unroll 1
    for (int iter = 0; iter < 3; iter++) {
        // softmax over capsule axis k at each position l; masked l -> exactly 1/3
        if (t < LSEQ) {
            const float l0 = logits[t], l1 = logits[200 + t], l2 = logits[400 + t];
            float w0, w1, w2;
            if (t < sl) {
                const float m  = fmaxf(l0, fmaxf(l1, l2));
                const float e0 = __expf(l0 - m), e1 = __expf(l1 - m), e2 = __expf(l2 - m);
                const float inv = __frcp_rn(e0 + e1 + e2);
                w0 = e0 * inv; w1 = e1 * inv; w2 = e2 * inv;
            } else {
                w0 = w1 = w2 = (1.f / 3.f);   // all-masked softmax == uniform
            }
            wts[t] = w0; wts[200 + t] = w1; wts[400 + t] = w2;
        }
        __syncthreads();

        // candidates[k][o] = sum_l wts[k][l] * M[l][o]
        if (t < 192) {
            const int k = t >> 6, o = t & 63;
            const float* wk = wts + k*200;
            float a0 = 0.f, a1 = 0.f;
            #pragma unroll 4
            for (int l = 0; l < LSEQ; l += 2) {
                a0 = fmaf(wk[l],     Ms[l*LP + o],       a0);
                a1 = fmaf(wk[l + 1], Ms[(l + 1)*LP + o], a1);
            }
            cand[t] = a0 + a1;
        }
        __syncthreads();

        // squash factor per capsule
        if (t < KCAP) {
            float sn = 0.f;
            #pragma unroll
            for (int o = 0; o < 64; o++) { const float v = cand[t*64 + o]; sn = fmaf(v, v, sn); }
            fac[t] = sn / ((1.f + sn) * sqrtf(sn + 1e-8f));
        }
        __syncthreads();

        if (iter < 2) {
            // logits[k][l] += fac[k] * (cand[k][:] . M[l][:])
            for (int idx = t; idx < 600; idx += 256) {
                const int k = idx / 200;
                const int l = idx - k*200;
                const float* ck = cand + k*64;
                const float* ml = Ms + l*LP;
                float a = 0.f;
                #pragma unroll 8
                for (int o = 0; o < 64; o++) a = fmaf(ck[o], ml[o], a);
                logits[idx] += fac[k] * a;
            }
            __syncthreads();
        } else {
            // final iteration: interests = fac[k] * cand[k][o]  -> out[n][k][o]
            if (t < 192) {
                const int k = t >> 6;
                out[n*192 + t] = fac[k] * cand[t];
            }
        }
    }
}

extern "C" void kernel_launch(void* const* d_in, const int* in_sizes, int n_in,
                              void* d_out, int out_size)
{
    const float* E  = (const float*)d_in[0];  // [N,200,64]
    const float* W  = (const float*)d_in[1];  // [64,64]
    const float* Lg = (const float*)d_in[2];  // [N,3,200]
    const int*   SL = (const int*)d_in[3];    // [N,1]
    float* out = (float*)d_out;               // [N,3,64]

    const int N = in_sizes[3];                // seq_len has N elements
    const int smem_bytes = SMEM_FLOATS * (int)sizeof(float);

    cudaFuncSetAttribute(caps_kernel,
                         cudaFuncAttributeMaxDynamicSharedMemorySize, smem_bytes);

    caps_kernel<<<N, 256, smem_bytes>>>(E, W, Lg, SL, out);
}

// round 2
// speedup vs baseline: 1.0738x; 1.0738x over previous
#include <cuda_runtime.h>

#define LSEQ 200
#define LP   68     // Ms row stride: 16B-aligned, conflict-free in both C-phase patterns
#define EST  132    // EsT row stride (l padded), 16B-aligned LDS.128, 2-way STS conflict only

// smem floats: Ws 4096 | EsT 64*132=8448 | Ms 200*68=13600 | logits 600 | wts 600 | cand 192 | fac 4
#define SMEM_FLOATS (4096 + 8448 + 13600 + 600 + 600 + 192 + 4)

__device__ __forceinline__ float2 ffma2(float2 a, float2 b, float2 c) {
    float2 r;
    asm("fma.rn.f32x2 %0, %1, %2, %3;"
        : "=l"(reinterpret_cast<unsigned long long&>(r))
        : "l"(reinterpret_cast<unsigned long long&>(a)),
          "l"(reinterpret_cast<unsigned long long&>(b)),
          "l"(reinterpret_cast<unsigned long long&>(c)));
    return r;
}

__global__ __launch_bounds__(256, 2)
void caps_kernel(const float* __restrict__ E,
                 const float* __restrict__ Wg,
                 const float* __restrict__ Lg,
                 const int*   __restrict__ SL,
                 float* __restrict__ out)
{
    extern __shared__ float sm[];
    float* Ws     = sm;                    // [64][64]
    float* EsT    = Ws + 4096;             // [64][EST]  (d-major transposed E chunk)
    float* Ms     = EsT + 64*EST;          // [200][LP]
    float* logits = Ms + LSEQ*LP;          // [600]
    float* wts    = logits + 600;          // [600]
    float* cand   = wts + 600;             // [192]
    float* fac    = cand + 192;            // [4]

    const int n = blockIdx.x;
    const int t = threadIdx.x;             // 0..255
    const int tx = t & 7;                  // col group: cols 8*tx .. 8*tx+7
    const int ty = t >> 3;                 // row group: rows 4*ty .. 4*ty+3 (within chunk)

    // ---- load W (16KB) + logits ----
    {
        const float4* w4 = reinterpret_cast<const float4*>(Wg);
        float4* s4 = reinterpret_cast<float4*>(Ws);
        #pragma unroll
        for (int i = 0; i < 4; i++) s4[t + 256*i] = w4[t + 256*i];
        const float* lg = Lg + n*600;
        #pragma unroll
        for (int i = t; i < 600; i += 256) logits[i] = lg[i];
    }
    const int sl = SL[n];
    __syncthreads();

    // ---- Phase B: Ms = E @ W, 2 chunks (128 + 72 rows), 4x8 register tile ----
    const float* En = E + (size_t)n * LSEQ * 64;
    #pragma unroll 1
    for (int chunk = 0; chunk < 2; chunk++) {
        const int base = chunk * 128;
        const int rows = chunk ? 72 : 128;

        // load E chunk from gmem (float4, coalesced) and transpose into EsT[d][l]
        const float4* e4 = reinterpret_cast<const float4*>(En + base*64);
        for (int f = t; f < rows*16; f += 256) {
            const int l = f >> 4, c = f & 15;
            const float4 v = e4[f];
            EsT[(4*c+0)*EST + l] = v.x;
            EsT[(4*c+1)*EST + l] = v.y;
            EsT[(4*c+2)*EST + l] = v.z;
            EsT[(4*c+3)*EST + l] = v.w;
        }
        __syncthreads();

        if (4*ty < rows) {
            float2 acc[4][4];
            #pragma unroll
            for (int i = 0; i < 4; i++)
                #pragma unroll
                for (int p = 0; p < 4; p++) acc[i][p] = make_float2(0.f, 0.f);

            #pragma unroll 4
            for (int d = 0; d < 64; d++) {
                const float4 a4 = *reinterpret_cast<const float4*>(&EsT[d*EST + 4*ty]);
                const float4 b0 = *reinterpret_cast<const float4*>(&Ws[d*64 + 8*tx]);
                const float4 b1 = *reinterpret_cast<const float4*>(&Ws[d*64 + 8*tx + 4]);
                const float2 bp[4] = { make_float2(b0.x,b0.y), make_float2(b0.z,b0.w),
                                       make_float2(b1.x,b1.y), make_float2(b1.z,b1.w) };
                const float av[4] = { a4.x, a4.y, a4.z, a4.w };
                #pragma unroll
                for (int i = 0; i < 4; i++) {
                    const float2 aa = make_float2(av[i], av[i]);
                    #pragma unroll
                    for (int p = 0; p < 4; p++)
                        acc[i][p] = ffma2(aa, bp[p], acc[i][p]);
                }
            }
            #pragma unroll
            for (int i = 0; i < 4; i++) {
                const int row = base + 4*ty + i;
                if (row < LSEQ) {
                    float4 s0 = make_float4(acc[i][0].x, acc[i][0].y, acc[i][1].x, acc[i][1].y);
                    float4 s1 = make_float4(acc[i][2].x, acc[i][2].y, acc[i][3].x, acc[i][3].y);
                    *reinterpret_cast<float4*>(&Ms[row*LP + 8*tx])     = s0;
                    *reinterpret_cast<float4*>(&Ms[row*LP + 8*tx + 4]) = s1;
                }
            }
        }
        __syncthreads();
    }

    // ---- Phase C: 3 routing iterations in smem ----
    #pragma unroll 1
    for (int iter = 0; iter < 3; iter++) {
        // softmax over capsule axis; fully-masked positions -> exactly 1/3
        if (t < LSEQ) {
            const float l0 = logits[t], l1 = logits[200 + t], l2 = logits[400 + t];
            float w0, w1, w2;
            if (t < sl) {
                const float m  = fmaxf(l0, fmaxf(l1, l2));
                const float e0 = __expf(l0 - m), e1 = __expf(l1 - m), e2 = __expf(l2 - m);
                const float inv = __frcp_rn(e0 + e1 + e2);
                w0 = e0 * inv; w1 = e1 * inv; w2 = e2 * inv;
            } else {
                w0 = w1 = w2 = (1.f / 3.f);
            }
            wts[t] = w0; wts[200 + t] = w1; wts[400 + t] = w2;
        }
        __syncthreads();

        // candidates[k][o] = sum_l wts[k][l] * Ms[l][o]   (packed over l pairs)
        if (t < 192) {
            const int k = t >> 6, o = t & 63;
            const float2* wk2 = reinterpret_cast<const float2*>(wts + k*200);
            float2 a0 = make_float2(0.f,0.f), a1 = make_float2(0.f,0.f);
            #pragma unroll 5
            for (int j = 0; j < 50; j++) {
                const float2 w0 = wk2[2*j], w1 = wk2[2*j+1];
                const float2 m0 = make_float2(Ms[(4*j+0)*LP + o], Ms[(4*j+1)*LP + o]);
                const float2 m1 = make_float2(Ms[(4*j+2)*LP + o], Ms[(4*j+3)*LP + o]);
                a0 = ffma2(w0, m0, a0);
                a1 = ffma2(w1, m1, a1);
            }
            cand[t] = a0.x + a0.y + a1.x + a1.y;
        }
        __syncthreads();

        // squash factor
        if (t < 3) {
            float sn = 0.f;
            #pragma unroll
            for (int o = 0; o < 64; o++) { const float v = cand[t*64 + o]; sn = fmaf(v, v, sn); }
            fac[t] = sn / ((1.f + sn) * sqrtf(sn + 1e-8f));
        }
        __syncthreads();

        if (iter < 2) {
            // logits[k][l] += fac[k] * (cand[k] . Ms[l])  — float4 loads, FFMA2
            #pragma unroll
            for (int r = 0; r < 3; r++) {
                const int idx = t + 256*r;
                if (idx < 600) {
                    const int k = (idx >= 400) ? 2 : ((idx >= 200) ? 1 : 0);
                    const int l = idx - 200*k;
                    const float4* ml4 = reinterpret_cast<const float4*>(Ms + l*LP);
                    const float4* ck4 = reinterpret_cast<const float4*>(cand + k*64);
                    float2 a0 = make_float2(0.f,0.f), a1 = make_float2(0.f,0.f);
                    #pragma unroll 8
                    for (int q = 0; q < 16; q++) {
                        const float4 m = ml4[q];
                        const float4 c2 = ck4[q];
                        a0 = ffma2(make_float2(m.x,m.y), make_float2(c2.x,c2.y), a0);
                        a1 = ffma2(make_float2(m.z,m.w), make_float2(c2.z,c2.w), a1);
                    }
                    logits[idx] += fac[k] * (a0.x + a0.y + a1.x + a1.y);
                }
            }
            __syncthreads();
        } else {
            if (t < 192) {
                const int k = t >> 6;
                out[n*192 + t] = fac[k] * cand[t];
            }
        }
    }
}

extern "C" void kernel_launch(void* const* d_in, const int* in_sizes, int n_in,
                              void* d_out, int out_size)
{
    const float* E  = (const float*)d_in[0];  // [N,200,64]
    const float* W  = (const float*)d_in[1];  // [64,64]
    const float* Lg = (const float*)d_in[2];  // [N,3,200]
    const int*   SL = (const int*)d_in[3];    // [N,1]
    float* out = (float*)d_out;               // [N,3,64]

    const int N = in_sizes[3];
    const int smem_bytes = SMEM_FLOATS * (int)sizeof(float);

    cudaFuncSetAttribute(caps_kernel,
                         cudaFuncAttributeMaxDynamicSharedMemorySize, smem_bytes);

    caps_kernel<<<N, 256, smem_bytes>>>(E, W, Lg, SL, out);
}

// round 3
// speedup vs baseline: 1.5604x; 1.4531x over previous
#include <cuda_runtime.h>

#define LSEQ 200
#define LP   68

// smem (floats)
#define OFF_WS   0
#define OFF_POOL 4096                 // Es chunk (<=8192) ; later wtsI + partials
#define OFF_MS   (4096 + 8192)        // 12288
#define OFF_CAND (OFF_MS + LSEQ*LP)   // 25888
#define OFF_FAC  (OFF_CAND + 192)     // 26080
#define SMEM_FLOATS (OFF_FAC + 4)     // 26084 floats = 104336 B  (2 CTAs/SM)

#define OFF_WTSI OFF_POOL             // [l][4], 800 floats
#define OFF_PART (OFF_POOL + 1024)    // [8][3][64] = 1536 floats

__device__ __forceinline__ float2 ffma2(float2 a, float2 b, float2 c) {
    float2 r;
    asm("fma.rn.f32x2 %0, %1, %2, %3;"
        : "=l"(reinterpret_cast<unsigned long long&>(r))
        : "l"(reinterpret_cast<unsigned long long&>(a)),
          "l"(reinterpret_cast<unsigned long long&>(b)),
          "l"(reinterpret_cast<unsigned long long&>(c)));
    return r;
}

__global__ __launch_bounds__(256, 2)
void caps_kernel(const float* __restrict__ E,
                 const float* __restrict__ Wg,
                 const float* __restrict__ Lg,
                 const int*   __restrict__ SL,
                 float* __restrict__ out)
{
    extern __shared__ float sm[];
    const int n = blockIdx.x;
    const int t = threadIdx.x;

    // ---- load W into smem ----
    {
        const float4* w4 = reinterpret_cast<const float4*>(Wg);
        float4* s4 = reinterpret_cast<float4*>(sm + OFF_WS);
        #pragma unroll
        for (int i = 0; i < 4; i++) s4[t + 256*i] = w4[t + 256*i];
    }
    const int sl = SL[n];

    // logits live in registers: thread t owns position l = t (t < 200)
    const bool haveL = (t < LSEQ);
    float lg0 = 0.f, lg1 = 0.f, lg2 = 0.f;
    if (haveL) {
        const float* lgp = Lg + n*600 + t;
        lg0 = lgp[0]; lg1 = lgp[200]; lg2 = lgp[400];
    }
    __syncthreads();

    // ---- Phase B: Ms = E @ W  (8x8 register tile, swizzled Es, FFMA2) ----
    const float* En = E + (size_t)n * LSEQ * 64;
    float4* Es4 = reinterpret_cast<float4*>(sm + OFF_POOL);
    const float4* Ws4 = reinterpret_cast<const float4*>(sm + OFF_WS);

    #pragma unroll 1
    for (int chunk = 0; chunk < 2; chunk++) {
        const int base = chunk ? 128 : 0;
        const int rows = chunk ? 72 : 128;

        // stage E chunk, float4-swizzled: chunk q of local row lr at (q ^ ((lr>>3)&7))
        const float4* e4 = reinterpret_cast<const float4*>(En + base*64);
        for (int f = t; f < rows*16; f += 256) {
            const int lr = f >> 4, q = f & 15;
            Es4[lr*16 + (q ^ ((lr >> 3) & 7))] = e4[f];
        }
        __syncthreads();

        if (t < rows) {
            const int rg = t >> 3;        // local row group (8 rows)
            const int tx = t & 7;         // col group (8 cols)
            const int key = rg & 7;

            float2 acc[8][4];
            #pragma unroll
            for (int i = 0; i < 8; i++)
                #pragma unroll
                for (int p = 0; p < 4; p++) acc[i][p] = make_float2(0.f, 0.f);

            #pragma unroll 4
            for (int q = 0; q < 16; q++) {
                float2 b2[4][4];
                #pragma unroll
                for (int j = 0; j < 4; j++) {
                    const float4 p0 = Ws4[(4*q + j)*16 + 2*tx];
                    const float4 p1 = Ws4[(4*q + j)*16 + 2*tx + 1];
                    b2[j][0] = make_float2(p0.x, p0.y);
                    b2[j][1] = make_float2(p0.z, p0.w);
                    b2[j][2] = make_float2(p1.x, p1.y);
                    b2[j][3] = make_float2(p1.z, p1.w);
                }
                #pragma unroll
                for (int i = 0; i < 8; i++) {
                    const float4 a = Es4[(8*rg + i)*16 + (q ^ key)];
                    const float av[4] = { a.x, a.y, a.z, a.w };
                    #pragma unroll
                    for (int j = 0; j < 4; j++) {
                        const float2 aa = make_float2(av[j], av[j]);
                        #pragma unroll
                        for (int p = 0; p < 4; p++)
                            acc[i][p] = ffma2(aa, b2[j][p], acc[i][p]);
                    }
                }
            }
            #pragma unroll
            for (int i = 0; i < 8; i++) {
                const int row = base + 8*rg + i;
                float4 s0 = make_float4(acc[i][0].x, acc[i][0].y, acc[i][1].x, acc[i][1].y);
                float4 s1 = make_float4(acc[i][2].x, acc[i][2].y, acc[i][3].x, acc[i][3].y);
                *reinterpret_cast<float4*>(sm + OFF_MS + row*LP + 8*tx)     = s0;
                *reinterpret_cast<float4*>(sm + OFF_MS + row*LP + 8*tx + 4) = s1;
            }
        }
        __syncthreads();
    }

    // ---- Phase C: 3 routing iterations ----
    const bool valid = (t < sl);

    #pragma unroll 1
    for (int iter = 0; iter < 3; iter++) {
        // softmax over capsules, in registers; masked -> exactly 1/3
        if (haveL) {
            float w0, w1, w2;
            if (valid) {
                const float m  = fmaxf(lg0, fmaxf(lg1, lg2));
                const float e0 = __expf(lg0 - m), e1 = __expf(lg1 - m), e2 = __expf(lg2 - m);
                const float inv = __frcp_rn(e0 + e1 + e2);
                w0 = e0*inv; w1 = e1*inv; w2 = e2*inv;
            } else {
                w0 = w1 = w2 = (1.f/3.f);
            }
            *reinterpret_cast<float4*>(sm + OFF_WTSI + 4*t) = make_float4(w0, w1, w2, 0.f);
        }
        __syncthreads();

        // candidates partials: thread (o4, lq) computes all 3 capsules over 25 l's
        if (t < 128) {
            const int o4 = t & 15, lq = t >> 4;
            float2 c[3][2];
            #pragma unroll
            for (int k = 0; k < 3; k++) { c[k][0] = make_float2(0.f,0.f); c[k][1] = make_float2(0.f,0.f); }
            const int l0 = lq*25;
            #pragma unroll 5
            for (int j = 0; j < 25; j++) {
                const int l = l0 + j;
                const float4 m4 = *reinterpret_cast<const float4*>(sm + OFF_MS + l*LP + 4*o4);
                const float4 wv = *reinterpret_cast<const float4*>(sm + OFF_WTSI + 4*l);
                const float2 mlo = make_float2(m4.x, m4.y), mhi = make_float2(m4.z, m4.w);
                c[0][0] = ffma2(make_float2(wv.x, wv.x), mlo, c[0][0]);
                c[0][1] = ffma2(make_float2(wv.x, wv.x), mhi, c[0][1]);
                c[1][0] = ffma2(make_float2(wv.y, wv.y), mlo, c[1][0]);
                c[1][1] = ffma2(make_float2(wv.y, wv.y), mhi, c[1][1]);
                c[2][0] = ffma2(make_float2(wv.z, wv.z), mlo, c[2][0]);
                c[2][1] = ffma2(make_float2(wv.z, wv.z), mhi, c[2][1]);
            }
            #pragma unroll
            for (int k = 0; k < 3; k++)
                *reinterpret_cast<float4*>(sm + OFF_PART + (lq*3 + k)*64 + 4*o4) =
                    make_float4(c[k][0].x, c[k][0].y, c[k][1].x, c[k][1].y);
        }
        __syncthreads();

        // reduce partials -> cand[k][o]
        if (t < 192) {
            const int k = t >> 6, o = t & 63;
            float s = 0.f;
            #pragma unroll
            for (int lq = 0; lq < 8; lq++) s += sm[OFF_PART + (lq*3 + k)*64 + o];
            sm[OFF_CAND + t] = s;
        }
        __syncthreads();

        // squash factor via warp reduce (one warp per capsule)
        if (t < 96) {
            const int k = t >> 5, lane = t & 31;
            const float v1 = sm[OFF_CAND + k*64 + lane];
            const float v2 = sm[OFF_CAND + k*64 + 32 + lane];
            float s = v1*v1 + v2*v2;
            #pragma unroll
            for (int off = 16; off; off >>= 1) s += __shfl_xor_sync(0xffffffffu, s, off);
            if (lane == 0) sm[OFF_FAC + k] = s / ((1.f + s) * sqrtf(s + 1e-8f));
        }
        __syncthreads();

        if (iter < 2) {
            // logits[k][l] += fac[k] * (cand[k] . Ms[l]) — Ms read once for all 3 k
            if (haveL) {
                const float4* ml = reinterpret_cast<const float4*>(sm + OFF_MS + t*LP);
                const float4* c0 = reinterpret_cast<const float4*>(sm + OFF_CAND);
                const float4* c1 = reinterpret_cast<const float4*>(sm + OFF_CAND + 64);
                const float4* c2 = reinterpret_cast<const float4*>(sm + OFF_CAND + 128);
                float2 a0 = make_float2(0.f,0.f), a1 = make_float2(0.f,0.f), a2 = make_float2(0.f,0.f);
                #pragma unroll 4
                for (int q = 0; q < 16; q++) {
                    const float4 m = ml[q];
                    const float2 mlo = make_float2(m.x, m.y), mhi = make_float2(m.z, m.w);
                    const float4 x0 = c0[q], x1 = c1[q], x2 = c2[q];
                    a0 = ffma2(mlo, make_float2(x0.x, x0.y), a0);
                    a0 = ffma2(mhi, make_float2(x0.z, x0.w), a0);
                    a1 = ffma2(mlo, make_float2(x1.x, x1.y), a1);
                    a1 = ffma2(mhi, make_float2(x1.z, x1.w), a1);
                    a2 = ffma2(mlo, make_float2(x2.x, x2.y), a2);
                    a2 = ffma2(mhi, make_float2(x2.z, x2.w), a2);
                }
                const float f0 = sm[OFF_FAC], f1 = sm[OFF_FAC + 1], f2 = sm[OFF_FAC + 2];
                lg0 += f0 * (a0.x + a0.y);
                lg1 += f1 * (a1.x + a1.y);
                lg2 += f2 * (a2.x + a2.y);
            }
            // no sync needed: next write touching CAND/FAC is >=2 syncs away
        } else {
            if (t < 192)
                out[n*192 + t] = sm[OFF_FAC + (t >> 6)] * sm[OFF_CAND + t];
        }
    }
}

extern "C" void kernel_launch(void* const* d_in, const int* in_sizes, int n_in,
                              void* d_out, int out_size)
{
    const float* E  = (const float*)d_in[0];  // [N,200,64]
    const float* W  = (const float*)d_in[1];  // [64,64]
    const float* Lg = (const float*)d_in[2];  // [N,3,200]
    const int*   SL = (const int*)d_in[3];    // [N,1]
    float* out = (float*)d_out;               // [N,3,64]

    const int N = in_sizes[3];
    const int smem_bytes = SMEM_FLOATS * (int)sizeof(float);

    cudaFuncSetAttribute(caps_kernel,
                         cudaFuncAttributeMaxDynamicSharedMemorySize, smem_bytes);

    caps_kernel<<<N, 256, smem_bytes>>>(E, W, Lg, SL, out);
}

// round 5
// speedup vs baseline: 2.7939x; 1.7904x over previous
#include <cuda_runtime.h>
#include <cstdint>

#define LSEQ 200
#define LP   68

// ---- smem float offsets ----
#define OFF_AF   0            // A fragments: 13*8 tiles * 132 floats = 13728 ; later Ms[200][68]=13600
#define OFF_MS   0
#define OFF_BF   13728        // B fragments: 8*8 tiles * 66 floats = 4224
#define OFF_WTSI 17952        // [200][4]
#define OFF_PART 18752        // [8][3][64]
#define OFF_CAND 20288        // [192]
#define OFF_FAC  20480        // [4]
#define SMEM_FLOATS 20484     // 81936 B -> 2 CTAs/SM

__device__ __forceinline__ uint32_t to_tf32(float x) {
    uint32_t u;
    asm("cvt.rna.tf32.f32 %0, %1;" : "=r"(u) : "f"(x));
    return u;
}

__device__ __forceinline__ void mma_tf32(float& c0, float& c1, float& c2, float& c3,
                                         uint32_t a0, uint32_t a1, uint32_t a2, uint32_t a3,
                                         uint32_t b0, uint32_t b1) {
    asm volatile("mma.sync.aligned.m16n8k8.row.col.f32.tf32.tf32.f32 "
                 "{%0,%1,%2,%3}, {%4,%5,%6,%7}, {%8,%9}, {%0,%1,%2,%3};"
                 : "+f"(c0), "+f"(c1), "+f"(c2), "+f"(c3)
                 : "r"(a0), "r"(a1), "r"(a2), "r"(a3), "r"(b0), "r"(b1));
}

__device__ __forceinline__ float2 ffma2(float2 a, float2 b, float2 c) {
    float2 r;
    asm("fma.rn.f32x2 %0, %1, %2, %3;"
        : "=l"(reinterpret_cast<unsigned long long&>(r))
        : "l"(reinterpret_cast<unsigned long long&>(a)),
          "l"(reinterpret_cast<unsigned long long&>(b)),
          "l"(reinterpret_cast<unsigned long long&>(c)));
    return r;
}

__global__ __launch_bounds__(256, 2)
void caps_kernel(const float* __restrict__ E,
                 const float* __restrict__ Wg,
                 const float* __restrict__ Lg,
                 const int*   __restrict__ SL,
                 float* __restrict__ out)
{
    extern __shared__ float sm[];
    const int n = blockIdx.x;
    const int t = threadIdx.x;
    const int wid = t >> 5, lane = t & 31;

    // ---- stage B fragments: B[k=d][n=o] = W[d][o] ----
    // Bfrag tile (nb,kb): 66 floats; lane pair (b0,b1): b0=B[lane&3][lane>>2], b1=B[(lane&3)+4][lane>>2]
    {
        const float4* w4 = reinterpret_cast<const float4*>(Wg);
        #pragma unroll
        for (int i = 0; i < 4; i++) {
            const int f = t + 256*i;              // f < 1024
            const int d = f >> 4;
            const float4 v = w4[f];
            const float vv[4] = { v.x, v.y, v.z, v.w };
            #pragma unroll
            for (int j = 0; j < 4; j++) {
                const int o = 4*(f & 15) + j;
                const int nb = o >> 3, kb = d >> 3;
                const int ln = ((o & 7) << 2) | (d & 3);
                const int slot = ((d & 7) >> 2);
                sm[OFF_BF + (nb*8 + kb)*66 + ln*2 + slot] =
                    __uint_as_float(to_tf32(vv[j]));
            }
        }
    }

    // ---- stage A fragments: A[m=l][k=d] = E[l][d], rows 0..199 (mb12 upper half garbage) ----
    // Afrag tile (mb,kb): 132 floats; lane quad (a0,a1,a2,a3):
    //   a0=A[r][c], a1=A[r+8][c], a2=A[r][c+4], a3=A[r+8][c+4], r=lane>>2, c=lane&3 (+8*kb on k)
    {
        const float4* e4 = reinterpret_cast<const float4*>(E + (size_t)n * LSEQ * 64);
        #pragma unroll
        for (int i = 0; i < 13; i++) {
            const int f = t + 256*i;              // f < 3200
            if (f < 3200) {
                const int g = f >> 4, q = f & 15;
                const float4 v = e4[f];
                const float vv[4] = { v.x, v.y, v.z, v.w };
                const int mb = g >> 4;
                const int kb = q >> 1;
                const int rhigh = (g >> 3) & 1;
                const int chalf = q & 1;
                const int slot = rhigh | (chalf << 1);
                const int base = OFF_AF + (mb*8 + kb)*132;
                const int lnbase = (g & 7) << 2;
                #pragma unroll
                for (int j = 0; j < 4; j++)
                    sm[base + (lnbase | j)*4 + slot] = __uint_as_float(to_tf32(vv[j]));
            }
        }
    }

    // logits in registers: thread t owns position l = t (t < 200)
    const bool haveL = (t < LSEQ);
    float lg0 = 0.f, lg1 = 0.f, lg2 = 0.f;
    if (haveL) {
        const float* lgp = Lg + n*600 + t;
        lg0 = lgp[0]; lg1 = lgp[200]; lg2 = lgp[400];
    }
    const int sl = SL[n];
    __syncthreads();

    // ---- Phase B mma: warp (wm = wid>>1 owns m-blocks, wn = wid&1 owns 4 n-blocks) ----
    const int wm = wid >> 1, wn = wid & 1;
    const int mb_base = (wm == 0) ? 0 : (1 + 3*wm);      // 0,4,7,10
    const int mbcnt   = (wm == 0) ? 4 : 3;

    float acc[4][4][4];
    #pragma unroll
    for (int a = 0; a < 4; a++)
        #pragma unroll
        for (int b = 0; b < 4; b++)
            #pragma unroll
            for (int c = 0; c < 4; c++) acc[a][b][c] = 0.f;

    #pragma unroll
    for (int kb = 0; kb < 8; kb++) {
        uint32_t bf[4][2];
        #pragma unroll
        for (int nbl = 0; nbl < 4; nbl++) {
            const int nb = wn*4 + nbl;
            const uint2 bv = *reinterpret_cast<const uint2*>(
                sm + OFF_BF + (nb*8 + kb)*66 + lane*2);
            bf[nbl][0] = bv.x; bf[nbl][1] = bv.y;
        }
        #pragma unroll
        for (int mbl = 0; mbl < 4; mbl++) {
            if (mbl < mbcnt) {
                const int mb = mb_base + mbl;
                const uint4 av = *reinterpret_cast<const uint4*>(
                    sm + OFF_AF + (mb*8 + kb)*132 + lane*4);
                #pragma unroll
                for (int nbl = 0; nbl < 4; nbl++)
                    mma_tf32(acc[mbl][nbl][0], acc[mbl][nbl][1],
                             acc[mbl][nbl][2], acc[mbl][nbl][3],
                             av.x, av.y, av.z, av.w, bf[nbl][0], bf[nbl][1]);
            }
        }
    }
    __syncthreads();   // all warps done reading Afrag; region becomes Ms

    // ---- epilogue: accum -> Ms[l][LP] ----
    {
        const int r_lo = lane >> 2;
        const int cbase = 2*(lane & 3);
        #pragma unroll
        for (int mbl = 0; mbl < 4; mbl++) {
            if (mbl < mbcnt) {
                const int mb = mb_base + mbl;
                const int r0 = mb*16 + r_lo, r1 = r0 + 8;
                #pragma unroll
                for (int nbl = 0; nbl < 4; nbl++) {
                    const int nn = (wn*4 + nbl)*8 + cbase;
                    *reinterpret_cast<float2*>(sm + OFF_MS + r0*LP + nn) =
                        make_float2(acc[mbl][nbl][0], acc[mbl][nbl][1]);
                    if (r1 < LSEQ)
                        *reinterpret_cast<float2*>(sm + OFF_MS + r1*LP + nn) =
                            make_float2(acc[mbl][nbl][2], acc[mbl][nbl][3]);
                }
            }
        }
    }
    __syncthreads();

    // ---- Phase C: 3 routing iterations (as R3) ----
    const bool valid = (t < sl);

    #pragma unroll 1
    for (int iter = 0; iter < 3; iter++) {
        if (haveL) {
            float w0, w1, w2;
            if (valid) {
                const float m  = fmaxf(lg0, fmaxf(lg1, lg2));
                const float e0 = __expf(lg0 - m), e1 = __expf(lg1 - m), e2 = __expf(lg2 - m);
                const float inv = __frcp_rn(e0 + e1 + e2);
                w0 = e0*inv; w1 = e1*inv; w2 = e2*inv;
            } else {
                w0 = w1 = w2 = (1.f/3.f);
            }
            *reinterpret_cast<float4*>(sm + OFF_WTSI + 4*t) = make_float4(w0, w1, w2, 0.f);
        }
        __syncthreads();

        // candidate partials: thread (o4 = t&15, lq = t>>4) covers 25 l's, all 3 k
        if (t < 128) {
            const int o4 = t & 15, lq = t >> 4;
            float2 c[3][2];
            #pragma unroll
            for (int k = 0; k < 3; k++) { c[k][0] = make_float2(0.f,0.f); c[k][1] = make_float2(0.f,0.f); }
            const int l0 = lq*25;
            #pragma unroll 5
            for (int j = 0; j < 25; j++) {
                const int l = l0 + j;
                const float4 m4 = *reinterpret_cast<const float4*>(sm + OFF_MS + l*LP + 4*o4);
                const float4 wv = *reinterpret_cast<const float4*>(sm + OFF_WTSI + 4*l);
                const float2 mlo = make_float2(m4.x, m4.y), mhi = make_float2(m4.z, m4.w);
                c[0][0] = ffma2(make_float2(wv.x, wv.x), mlo, c[0][0]);
                c[0][1] = ffma2(make_float2(wv.x, wv.x), mhi, c[0][1]);
                c[1][0] = ffma2(make_float2(wv.y, wv.y), mlo, c[1][0]);
                c[1][1] = ffma2(make_float2(wv.y, wv.y), mhi, c[1][1]);
                c[2][0] = ffma2(make_float2(wv.z, wv.z), mlo, c[2][0]);
                c[2][1] = ffma2(make_float2(wv.z, wv.z), mhi, c[2][1]);
            }
            #pragma unroll
            for (int k = 0; k < 3; k++)
                *reinterpret_cast<float4*>(sm + OFF_PART + (lq*3 + k)*64 + 4*o4) =
                    make_float4(c[k][0].x, c[k][0].y, c[k][1].x, c[k][1].y);
        }
        __syncthreads();

        if (t < 192) {
            const int k = t >> 6, o = t & 63;
            float s = 0.f;
            #pragma unroll
            for (int lq = 0; lq < 8; lq++) s += sm[OFF_PART + (lq*3 + k)*64 + o];
            sm[OFF_CAND + t] = s;
        }
        __syncthreads();

        if (t < 96) {
            const int k = t >> 5, ln = t & 31;
            const float v1 = sm[OFF_CAND + k*64 + ln];
            const float v2 = sm[OFF_CAND + k*64 + 32 + ln];
            float s = v1*v1 + v2*v2;
            #pragma unroll
            for (int off = 16; off; off >>= 1) s += __shfl_xor_sync(0xffffffffu, s, off);
            if (ln == 0) sm[OFF_FAC + k] = s / ((1.f + s) * sqrtf(s + 1e-8f));
        }
        __syncthreads();

        if (iter < 2) {
            if (haveL) {
                const float4* ml = reinterpret_cast<const float4*>(sm + OFF_MS + t*LP);
                const float4* c0 = reinterpret_cast<const float4*>(sm + OFF_CAND);
                const float4* c1 = reinterpret_cast<const float4*>(sm + OFF_CAND + 64);
                const float4* c2 = reinterpret_cast<const float4*>(sm + OFF_CAND + 128);
                float2 a0 = make_float2(0.f,0.f), a1 = make_float2(0.f,0.f), a2 = make_float2(0.f,0.f);
                #pragma unroll 4
                for (int q = 0; q < 16; q++) {
                    const float4 m = ml[q];
                    const float2 mlo = make_float2(m.x, m.y), mhi = make_float2(m.z, m.w);
                    const float4 x0 = c0[q], x1 = c1[q], x2 = c2[q];
                    a0 = ffma2(mlo, make_float2(x0.x, x0.y), a0);
                    a0 = ffma2(mhi, make_float2(x0.z, x0.w), a0);
                    a1 = ffma2(mlo, make_float2(x1.x, x1.y), a1);
                    a1 = ffma2(mhi, make_float2(x1.z, x1.w), a1);
                    a2 = ffma2(mlo, make_float2(x2.x, x2.y), a2);
                    a2 = ffma2(mhi, make_float2(x2.z, x2.w), a2);
                }
                const float f0 = sm[OFF_FAC], f1 = sm[OFF_FAC + 1], f2 = sm[OFF_FAC + 2];
                lg0 += f0 * (a0.x + a0.y);
                lg1 += f1 * (a1.x + a1.y);
                lg2 += f2 * (a2.x + a2.y);
            }
        } else {
            if (t < 192)
                out[n*192 + t] = sm[OFF_FAC + (t >> 6)] * sm[OFF_CAND + t];
        }
    }
}

extern "C" void kernel_launch(void* const* d_in, const int* in_sizes, int n_in,
                              void* d_out, int out_size)
{
    const float* E  = (const float*)d_in[0];  // [N,200,64]
    const float* W  = (const float*)d_in[1];  // [64,64]
    const float* Lg = (const float*)d_in[2];  // [N,3,200]
    const int*   SL = (const int*)d_in[3];    // [N,1]
    float* out = (float*)d_out;               // [N,3,64]

    const int N = in_sizes[3];
    const int smem_bytes = SMEM_FLOATS * (int)sizeof(float);

    cudaFuncSetAttribute(caps_kernel,
                         cudaFuncAttributeMaxDynamicSharedMemorySize, smem_bytes);

    caps_kernel<<<N, 256, smem_bytes>>>(E, W, Lg, SL, out);
}

// round 6
// speedup vs baseline: 2.8108x; 1.0061x over previous
#include <cuda_runtime.h>
#include <cstdint>

#define LSEQ 200
#define LP   68

// ---- smem float offsets ----
// A (tf32, row-major [200][68]) lives at 0; after MMA the same region becomes Ms.
#define OFF_MS   0
#define OFF_BF   13600         // B fragments: 8*8 tiles * 66 floats = 4224 (dead after MMA)
#define OFF_WTSI OFF_BF        // [200][4] = 800   (aliases BF in Phase C)
#define OFF_PART (OFF_BF+800)  // [16][3][64] = 3072
#define OFF_CAND (OFF_BF+3872) // [192]
#define OFF_FAC  (OFF_BF+4064) // [4]
#define SMEM_FLOATS (OFF_BF + 4224)   // 17824 floats = 71296 B

__device__ __forceinline__ uint32_t to_tf32(float x) {
    uint32_t u;
    asm("cvt.rna.tf32.f32 %0, %1;" : "=r"(u) : "f"(x));
    return u;
}

__device__ __forceinline__ void mma_tf32(float& c0, float& c1, float& c2, float& c3,
                                         uint32_t a0, uint32_t a1, uint32_t a2, uint32_t a3,
                                         uint32_t b0, uint32_t b1) {
    asm volatile("mma.sync.aligned.m16n8k8.row.col.f32.tf32.tf32.f32 "
                 "{%0,%1,%2,%3}, {%4,%5,%6,%7}, {%8,%9}, {%0,%1,%2,%3};"
                 : "+f"(c0), "+f"(c1), "+f"(c2), "+f"(c3)
                 : "r"(a0), "r"(a1), "r"(a2), "r"(a3), "r"(b0), "r"(b1));
}

__device__ __forceinline__ float2 ffma2(float2 a, float2 b, float2 c) {
    float2 r;
    asm("fma.rn.f32x2 %0, %1, %2, %3;"
        : "=l"(reinterpret_cast<unsigned long long&>(r))
        : "l"(reinterpret_cast<unsigned long long&>(a)),
          "l"(reinterpret_cast<unsigned long long&>(b)),
          "l"(reinterpret_cast<unsigned long long&>(c)));
    return r;
}

__global__ __launch_bounds__(256, 2)
void caps_kernel(const float* __restrict__ E,
                 const float* __restrict__ Wg,
                 const float* __restrict__ Lg,
                 const int*   __restrict__ SL,
                 float* __restrict__ out)
{
    extern __shared__ float sm[];
    const int n = blockIdx.x;
    const int t = threadIdx.x;
    const int wid = t >> 5, lane = t & 31;

    // ---- stage B fragments (as R5): tile (nb,kb) = 66 floats ----
    {
        const float4* w4 = reinterpret_cast<const float4*>(Wg);
        #pragma unroll
        for (int i = 0; i < 4; i++) {
            const int f = t + 256*i;              // f < 1024
            const int d = f >> 4;
            const float4 v = w4[f];
            const float vv[4] = { v.x, v.y, v.z, v.w };
            #pragma unroll
            for (int j = 0; j < 4; j++) {
                const int o = 4*(f & 15) + j;
                const int nb = o >> 3, kb = d >> 3;
                const int ln = ((o & 7) << 2) | (d & 3);
                const int slot = ((d & 7) >> 2);
                sm[OFF_BF + (nb*8 + kb)*66 + ln*2 + slot] =
                    __uint_as_float(to_tf32(vv[j]));
            }
        }
    }

    // ---- stage A row-major [200][68] (tf32), vectorized ----
    {
        const float4* e4 = reinterpret_cast<const float4*>(E + (size_t)n * LSEQ * 64);
        #pragma unroll
        for (int i = 0; i < 13; i++) {
            const int f = t + 256*i;              // f < 3200
            if (f < 3200) {
                const int l = f >> 4, q = f & 15;
                const float4 v = e4[f];
                uint4 u;
                u.x = to_tf32(v.x); u.y = to_tf32(v.y);
                u.z = to_tf32(v.z); u.w = to_tf32(v.w);
                *reinterpret_cast<uint4*>(sm + OFF_MS + l*LP + 4*q) = u;
            }
        }
    }

    // logits in registers: thread t owns position l = t (t < 200)
    const bool haveL = (t < LSEQ);
    float lg0 = 0.f, lg1 = 0.f, lg2 = 0.f;
    if (haveL) {
        const float* lgp = Lg + n*600 + t;
        lg0 = lgp[0]; lg1 = lgp[200]; lg2 = lgp[400];
    }
    const int sl = SL[n];
    __syncthreads();

    // ---- Phase B mma: warp (wm owns m-blocks, wn owns 4 n-blocks) ----
    const int wm = wid >> 1, wn = wid & 1;
    const int mb_base = (wm == 0) ? 0 : (1 + 3*wm);      // 0,4,7,10
    const int mbcnt   = (wm == 0) ? 4 : 3;
    const int r_lo = lane >> 2, c_lo = lane & 3;

    float acc[4][4][4];
    #pragma unroll
    for (int a = 0; a < 4; a++)
        #pragma unroll
        for (int b = 0; b < 4; b++)
            #pragma unroll
            for (int c = 0; c < 4; c++) acc[a][b][c] = 0.f;

    #pragma unroll
    for (int kb = 0; kb < 8; kb++) {
        uint32_t bf[4][2];
        #pragma unroll
        for (int nbl = 0; nbl < 4; nbl++) {
            const int nb = wn*4 + nbl;
            const uint2 bv = *reinterpret_cast<const uint2*>(
                sm + OFF_BF + (nb*8 + kb)*66 + lane*2);
            bf[nbl][0] = bv.x; bf[nbl][1] = bv.y;
        }
        #pragma unroll
        for (int mbl = 0; mbl < 4; mbl++) {
            if (mbl < mbcnt) {
                const int mb = mb_base + mbl;
                const float* Ap = sm + OFF_MS + (mb*16 + r_lo)*LP + kb*8 + c_lo;
                const uint32_t a0 = __float_as_uint(Ap[0]);
                const uint32_t a1 = __float_as_uint(Ap[8*LP]);
                const uint32_t a2 = __float_as_uint(Ap[4]);
                const uint32_t a3 = __float_as_uint(Ap[8*LP + 4]);
                #pragma unroll
                for (int nbl = 0; nbl < 4; nbl++)
                    mma_tf32(acc[mbl][nbl][0], acc[mbl][nbl][1],
                             acc[mbl][nbl][2], acc[mbl][nbl][3],
                             a0, a1, a2, a3, bf[nbl][0], bf[nbl][1]);
            }
        }
    }
    __syncthreads();   // all MMA reads done; A region becomes Ms, BF becomes Phase-C pool

    // ---- epilogue: accum -> Ms[l][LP] ----
    {
        const int cbase = 2*c_lo;
        #pragma unroll
        for (int mbl = 0; mbl < 4; mbl++) {
            if (mbl < mbcnt) {
                const int mb = mb_base + mbl;
                const int r0 = mb*16 + r_lo, r1 = r0 + 8;
                #pragma unroll
                for (int nbl = 0; nbl < 4; nbl++) {
                    const int nn = (wn*4 + nbl)*8 + cbase;
                    *reinterpret_cast<float2*>(sm + OFF_MS + r0*LP + nn) =
                        make_float2(acc[mbl][nbl][0], acc[mbl][nbl][1]);
                    if (r1 < LSEQ)
                        *reinterpret_cast<float2*>(sm + OFF_MS + r1*LP + nn) =
                            make_float2(acc[mbl][nbl][2], acc[mbl][nbl][3]);
                }
            }
        }
    }
    __syncthreads();

    // ---- Phase C: 3 routing iterations ----
    const bool valid = (t < sl);

    #pragma unroll 1
    for (int iter = 0; iter < 3; iter++) {
        if (haveL) {
            float w0, w1, w2;
            if (valid) {
                const float m  = fmaxf(lg0, fmaxf(lg1, lg2));
                const float e0 = __expf(lg0 - m), e1 = __expf(lg1 - m), e2 = __expf(lg2 - m);
                const float inv = __frcp_rn(e0 + e1 + e2);
                w0 = e0*inv; w1 = e1*inv; w2 = e2*inv;
            } else {
                w0 = w1 = w2 = (1.f/3.f);
            }
            *reinterpret_cast<float4*>(sm + OFF_WTSI + 4*t) = make_float4(w0, w1, w2, 0.f);
        }
        __syncthreads();

        // candidate partials: all 8 warps; thread (o4 = t&15, lq = t>>4) covers 13 l's
        {
            const int o4 = t & 15, lq = t >> 4;
            float2 c[3][2];
            #pragma unroll
            for (int k = 0; k < 3; k++) { c[k][0] = make_float2(0.f,0.f); c[k][1] = make_float2(0.f,0.f); }
            const int l0 = lq*13;
            #pragma unroll
            for (int j = 0; j < 13; j++) {
                const int l = l0 + j;
                if (l < LSEQ) {
                    const float4 m4 = *reinterpret_cast<const float4*>(sm + OFF_MS + l*LP + 4*o4);
                    const float4 wv = *reinterpret_cast<const float4*>(sm + OFF_WTSI + 4*l);
                    const float2 mlo = make_float2(m4.x, m4.y), mhi = make_float2(m4.z, m4.w);
                    c[0][0] = ffma2(make_float2(wv.x, wv.x), mlo, c[0][0]);
                    c[0][1] = ffma2(make_float2(wv.x, wv.x), mhi, c[0][1]);
                    c[1][0] = ffma2(make_float2(wv.y, wv.y), mlo, c[1][0]);
                    c[1][1] = ffma2(make_float2(wv.y, wv.y), mhi, c[1][1]);
                    c[2][0] = ffma2(make_float2(wv.z, wv.z), mlo, c[2][0]);
                    c[2][1] = ffma2(make_float2(wv.z, wv.z), mhi, c[2][1]);
                }
            }
            #pragma unroll
            for (int k = 0; k < 3; k++)
                *reinterpret_cast<float4*>(sm + OFF_PART + (lq*3 + k)*64 + 4*o4) =
                    make_float4(c[k][0].x, c[k][0].y, c[k][1].x, c[k][1].y);
        }
        __syncthreads();

        if (t < 192) {
            const int k = t >> 6, o = t & 63;
            float s = 0.f;
            #pragma unroll
            for (int lq = 0; lq < 16; lq++) s += sm[OFF_PART + (lq*3 + k)*64 + o];
            sm[OFF_CAND + t] = s;
        }
        __syncthreads();

        if (t < 96) {
            const int k = t >> 5, ln = t & 31;
            const float v1 = sm[OFF_CAND + k*64 + ln];
            const float v2 = sm[OFF_CAND + k*64 + 32 + ln];
            float s = v1*v1 + v2*v2;
            #pragma unroll
            for (int off = 16; off; off >>= 1) s += __shfl_xor_sync(0xffffffffu, s, off);
            if (ln == 0) sm[OFF_FAC + k] = s / ((1.f + s) * sqrtf(s + 1e-8f));
        }
        __syncthreads();

        if (iter < 2) {
            if (haveL) {
                const float4* ml = reinterpret_cast<const float4*>(sm + OFF_MS + t*LP);
                const float4* c0 = reinterpret_cast<const float4*>(sm + OFF_CAND);
                const float4* c1 = reinterpret_cast<const float4*>(sm + OFF_CAND + 64);
                const float4* c2 = reinterpret_cast<const float4*>(sm + OFF_CAND + 128);
                float2 a0 = make_float2(0.f,0.f), a1 = make_float2(0.f,0.f), a2 = make_float2(0.f,0.f);
                #pragma unroll 4
                for (int q = 0; q < 16; q++) {
                    const float4 m = ml[q];
                    const float2 mlo = make_float2(m.x, m.y), mhi = make_float2(m.z, m.w);
                    const float4 x0 = c0[q], x1 = c1[q], x2 = c2[q];
                    a0 = ffma2(mlo, make_float2(x0.x, x0.y), a0);
                    a0 = ffma2(mhi, make_float2(x0.z, x0.w), a0);
                    a1 = ffma2(mlo, make_float2(x1.x, x1.y), a1);
                    a1 = ffma2(mhi, make_float2(x1.z, x1.w), a1);
                    a2 = ffma2(mlo, make_float2(x2.x, x2.y), a2);
                    a2 = ffma2(mhi, make_float2(x2.z, x2.w), a2);
                }
                const float f0 = sm[OFF_FAC], f1 = sm[OFF_FAC + 1], f2 = sm[OFF_FAC + 2];
                lg0 += f0 * (a0.x + a0.y);
                lg1 += f1 * (a1.x + a1.y);
                lg2 += f2 * (a2.x + a2.y);
            }
        } else {
            if (t < 192)
                out[n*192 + t] = sm[OFF_FAC + (t >> 6)] * sm[OFF_CAND + t];
        }
    }
}

extern "C" void kernel_launch(void* const* d_in, const int* in_sizes, int n_in,
                              void* d_out, int out_size)
{
    const float* E  = (const float*)d_in[0];  // [N,200,64]
    const float* W  = (const float*)d_in[1];  // [64,64]
    const float* Lg = (const float*)d_in[2];  // [N,3,200]
    const int*   SL = (const int*)d_in[3];    // [N,1]
    float* out = (float*)d_out;               // [N,3,64]

    const int N = in_sizes[3];
    const int smem_bytes = SMEM_FLOATS * (int)sizeof(float);

    cudaFuncSetAttribute(caps_kernel,
                         cudaFuncAttributeMaxDynamicSharedMemorySize, smem_bytes);

    caps_kernel<<<N, 256, smem_bytes>>>(E, W, Lg, SL, out);
}